// round 13
// baseline (speedup 1.0000x reference)
#include <cuda_runtime.h>
#include <cuda_bf16.h>
#include <math.h>
#include <stdint.h>

#define B_SZ   2
#define T_SEQ  1024
#define BT     2048
#define NH     32
#define HDIM   128

// ================= scratch =================
__device__ float g_qkv[BT * 6144];
__device__ __nv_bfloat16 g_xh[BT * 4096], g_xl[BT * 4096];
__device__ __nv_bfloat16 g_ah[BT * 4096], g_al[BT * 4096];
__device__ __nv_bfloat16 g_qh[BT * 4096], g_ql[BT * 4096];
__device__ __nv_bfloat16 g_kh[BT * 1024], g_kl[BT * 1024];
__device__ __nv_bfloat16 g_vh[BT * 1024], g_vl[BT * 1024];
__device__ __nv_bfloat16 g_wqkvh[6144 * 4096], g_wqkvl[6144 * 4096];
__device__ __nv_bfloat16 g_woh[4096 * 4096], g_wol[4096 * 4096];
__device__ float4 g_ropetab[1024 * 64];

// ================= helpers =================
__device__ __forceinline__ uint32_t smem_u32(const void* p) {
    uint32_t a;
    asm("{ .reg .u64 t; cvta.to.shared.u64 t, %1; cvt.u32.u64 %0, t; }"
        : "=r"(a) : "l"(p));
    return a;
}
// GEMM tile swizzle: (rows)x32(k) bf16 tile
__device__ __forceinline__ uint32_t swz(uint32_t r, uint32_t u) {
    return ((r >> 1) << 7) | (((((r & 1) << 2) | u) ^ ((r >> 1) & 7)) << 4);
}
// attention tile swizzle: (rows)x128 bf16 tile, 16 16B-units/row
#define OFFA(r, u) (((uint32_t)(r)) * 256 + ((((uint32_t)(u)) ^ (((uint32_t)(r)) & 7)) << 4))

#define CP_ASYNC16(dst, src) \
    asm volatile("cp.async.cg.shared.global [%0], [%1], 16;" :: "r"(dst), "l"(src))
#define CP_COMMIT() asm volatile("cp.async.commit_group;" ::: "memory")
#define CP_WAIT0()  asm volatile("cp.async.wait_group 0;" ::: "memory")
#define CP_WAIT1()  asm volatile("cp.async.wait_group 1;" ::: "memory")
#define CP_WAIT2()  asm volatile("cp.async.wait_group 2;" ::: "memory")

#define LDSM4(r0, r1, r2, r3, a) \
    asm volatile("ldmatrix.sync.aligned.m8n8.x4.shared.b16 {%0,%1,%2,%3}, [%4];" \
        : "=r"(r0), "=r"(r1), "=r"(r2), "=r"(r3) : "r"(a))
#define LDSM4T(r0, r1, r2, r3, a) \
    asm volatile("ldmatrix.sync.aligned.m8n8.x4.trans.shared.b16 {%0,%1,%2,%3}, [%4];" \
        : "=r"(r0), "=r"(r1), "=r"(r2), "=r"(r3) : "r"(a))

#define MMA16816(c, a0, a1, a2, a3, b0, b1) \
    asm volatile("mma.sync.aligned.m16n8k16.row.col.f32.bf16.bf16.f32 " \
        "{%0,%1,%2,%3}, {%4,%5,%6,%7}, {%8,%9}, {%0,%1,%2,%3};" \
        : "+f"((c)[0]), "+f"((c)[1]), "+f"((c)[2]), "+f"((c)[3]) \
        : "r"(a0), "r"(a1), "r"(a2), "r"(a3), "r"(b0), "r"(b1))

__device__ __forceinline__ void pack_hl(float f0, float f1, uint32_t& h, uint32_t& l) {
    __nv_bfloat162 hh = __floats2bfloat162_rn(f0, f1);
    float r0 = f0 - __bfloat162float(hh.x);
    float r1 = f1 - __bfloat162float(hh.y);
    __nv_bfloat162 ll = __floats2bfloat162_rn(r0, r1);
    h = *(uint32_t*)&hh;
    l = *(uint32_t*)&ll;
}

// ============ rope table: tab[t][p] = (cos a0, sin a0, cos a1, sin a1) ============
// bitwise-identical math to the previous in-kernel rope computation
__global__ void ropetab_kernel(const int* __restrict__ sp, float4* __restrict__ tab)
{
    int i = blockIdx.x * blockDim.x + threadIdx.x;   // 0..65535
    int t = i >> 6, p = i & 63;
    int start = (sp == nullptr) ? 0 : *sp;
    float tt = (float)(start + t);
    const float lf = 9.210340371976184f;
    int j0 = (2 * p) & 63;
    float a0 = tt * expf(-(float)j0       * (lf / 64.f));
    float a1 = tt * expf(-(float)(j0 + 1) * (lf / 64.f));
    float c0, s0, c1, s1;
    sincosf(a0, &s0, &c0);
    sincosf(a1, &s1, &c1);
    tab[i] = make_float4(c0, s0, c1, s1);
}

// ============ split fp32 -> bf16 hi/lo (row-major dense) ============
__global__ void split_kernel(const float* __restrict__ in,
                             __nv_bfloat16* __restrict__ hi,
                             __nv_bfloat16* __restrict__ lo, int n4)
{
    int i = blockIdx.x * blockDim.x + threadIdx.x;
    if (i >= n4) return;
    float4 v = ((const float4*)in)[i];
    uint32_t h0, l0, h1, l1;
    pack_hl(v.x, v.y, h0, l0);
    pack_hl(v.z, v.w, h1, l1);
    ((uint2*)hi)[i] = make_uint2(h0, h1);
    ((uint2*)lo)[i] = make_uint2(l0, l1);
}

// ============ strided split: in[row*in_stride4 + c4] (float4 units) ============
__global__ void splitstride_kernel(const float* __restrict__ in, int in_stride4,
                                   int cols4, __nv_bfloat16* __restrict__ hi,
                                   __nv_bfloat16* __restrict__ lo, int n4)
{
    int i = blockIdx.x * blockDim.x + threadIdx.x;
    if (i >= n4) return;
    int row = i / cols4;
    int c4 = i - row * cols4;
    float4 v = ((const float4*)in)[(size_t)row * in_stride4 + c4];
    int o = row * cols4 + c4;
    uint32_t h0, l0, h1, l1;
    pack_hl(v.x, v.y, h0, l0);
    pack_hl(v.z, v.w, h1, l1);
    ((uint2*)hi)[o] = make_uint2(h0, h1);
    ((uint2*)lo)[o] = make_uint2(l0, l1);
}

// ============ transpose + split: W[K][N] fp32 -> Wt[N][K] bf16 hi/lo ============
__global__ __launch_bounds__(256) void tsplit2_kernel(
    const float* __restrict__ W, __nv_bfloat16* __restrict__ hi,
    __nv_bfloat16* __restrict__ lo, int K, int N)
{
    __shared__ float s[32][66];
    const int n0 = blockIdx.x * 32, k0 = blockIdx.y * 64;
    const int tid = threadIdx.x;
    #pragma unroll
    for (int i = 0; i < 8; i++) {
        int idx = tid + i * 256;
        int r = idx >> 5;
        int c = idx & 31;
        s[c][r] = W[(size_t)(k0 + r) * N + n0 + c];
    }
    __syncthreads();
    #pragma unroll
    for (int i = 0; i < 4; i++) {
        int p = tid + i * 256;
        int row = p >> 5;
        int pr = p & 31;
        float2 v = *(float2*)&s[row][pr * 2];
        uint32_t h, l;
        pack_hl(v.x, v.y, h, l);
        size_t o = (size_t)(n0 + row) * K + k0 + pr * 2;
        *(uint32_t*)(hi + o) = h;
        *(uint32_t*)(lo + o) = l;
    }
}

// ============ RoPE (table) + split (strided in/out) ============
__global__ void rope_split_kernel(const float* __restrict__ in, int in_stride,
                                  __nv_bfloat16* __restrict__ hi,
                                  __nv_bfloat16* __restrict__ lo, int out_stride,
                                  int total_pairs, const float4* __restrict__ tab,
                                  float scale)
{
    int idx = blockIdx.x * blockDim.x + threadIdx.x;
    if (idx >= total_pairs) return;
    int halfout = out_stride >> 1;
    int row = idx / halfout;
    int p   = idx - row * halfout;
    int c0  = p * 2;
    int pp  = (c0 & (HDIM - 1)) >> 1;
    float4 cs = tab[(row & (T_SEQ - 1)) * 64 + pp];
    const float* base = in + (size_t)row * in_stride + c0;
    float x0 = base[0], x1 = base[1];
    float y0 = (x0 * cs.x - x1 * cs.y) * scale;
    float y1 = (x1 * cs.z + x0 * cs.w) * scale;
    uint32_t h, l;
    pack_hl(y0, y1, h, l);
    *(uint32_t*)(hi + (size_t)row * out_stride + c0) = h;
    *(uint32_t*)(lo + (size_t)row * out_stride + c0) = l;
}

// ============ bf16x3 GEMM 128x256 (QKV and O) ============
#define KC      32
#define NSTB    4
#define A_TB    8192
#define B_TB    16384
#define STAGE_BB (2 * A_TB + 2 * B_TB)
#define BIG_SMEM (NSTB * STAGE_BB)

__global__ __launch_bounds__(256, 1) void gemm3_big_kernel(
    const __nv_bfloat16* __restrict__ Ah, const __nv_bfloat16* __restrict__ Al,
    const __nv_bfloat16* __restrict__ Bh, const __nv_bfloat16* __restrict__ Bl,
    float* __restrict__ C, int M, int N, int K)
{
    extern __shared__ char smem[];
    const uint32_t sb = smem_u32(smem);
    const int tid = threadIdx.x, wid = tid >> 5, lid = tid & 31;
    const int m0 = blockIdx.y * 128, n0 = blockIdx.x * 256;
    const int warp_m = wid & 1, warp_n = wid >> 1;
    const int NCH = K / KC;

    uint32_t rel_a[4][2], rel_b[4][2];
    {
        uint32_t ar = (uint32_t)(warp_m * 64 + (lid & 15));
        uint32_t au = (uint32_t)(lid >> 4);
        #pragma unroll
        for (int mi = 0; mi < 4; mi++)
            #pragma unroll
            for (int k16 = 0; k16 < 2; k16++)
                rel_a[mi][k16] = swz(ar + mi * 16, au + k16 * 2);
        uint32_t br = (uint32_t)(warp_n * 64 + (lid & 7) + ((lid >> 4) << 3));
        uint32_t bu = (uint32_t)((lid >> 3) & 1);
        #pragma unroll
        for (int ng = 0; ng < 4; ng++)
            #pragma unroll
            for (int k16 = 0; k16 < 2; k16++)
                rel_b[ng][k16] = swz(br + ng * 16, bu + k16 * 2);
    }

    float acc[4][8][4];
    #pragma unroll
    for (int mi = 0; mi < 4; mi++)
        #pragma unroll
        for (int ni = 0; ni < 8; ni++)
            #pragma unroll
            for (int j = 0; j < 4; j++) acc[mi][ni][j] = 0.f;

    auto load_stage = [&](int s, int chunk) {
        const int k0 = chunk * KC;
        const uint32_t st = sb + s * STAGE_BB;
        #pragma unroll
        for (int t = 0; t < 12; t++) {
            int g = t * 256 + tid;
            uint32_t dst;
            const __nv_bfloat16* src;
            if (g < 1024) {
                int r = (g & 511) >> 2, u = g & 3;
                dst = st + (g >> 9) * A_TB + swz(r, u);
                src = ((g >> 9) ? Al : Ah) + (size_t)(m0 + r) * K + k0 + u * 8;
            } else {
                int w = g - 1024;
                int r = (w & 1023) >> 2, u = w & 3;
                dst = st + 2 * A_TB + (w >> 10) * B_TB + swz(r, u);
                src = ((w >> 10) ? Bl : Bh) + (size_t)(n0 + r) * K + k0 + u * 8;
            }
            CP_ASYNC16(dst, src);
        }
    };

    load_stage(0, 0); CP_COMMIT();
    load_stage(1, 1); CP_COMMIT();
    load_stage(2, 2); CP_COMMIT();

    for (int i = 0; i < NCH; i++) {
        CP_WAIT2();
        __syncthreads();
        int nxt = i + NSTB - 1;
        if (nxt < NCH) load_stage(nxt % NSTB, nxt);
        CP_COMMIT();

        const uint32_t st = sb + (i % NSTB) * STAGE_BB;
        const uint32_t ah_b = st, al_b = st + A_TB;
        const uint32_t bh_b = st + 2 * A_TB, bl_b = st + 2 * A_TB + B_TB;

        #pragma unroll
        for (int k16 = 0; k16 < 2; k16++) {
            uint32_t afh[4][4], afl[4][4];
            #pragma unroll
            for (int mi = 0; mi < 4; mi++) {
                LDSM4(afh[mi][0], afh[mi][1], afh[mi][2], afh[mi][3], ah_b + rel_a[mi][k16]);
                LDSM4(afl[mi][0], afl[mi][1], afl[mi][2], afl[mi][3], al_b + rel_a[mi][k16]);
            }
            #pragma unroll
            for (int ng = 0; ng < 4; ng++) {
                uint32_t bfh[4], bfl[4];
                LDSM4(bfh[0], bfh[1], bfh[2], bfh[3], bh_b + rel_b[ng][k16]);
                LDSM4(bfl[0], bfl[1], bfl[2], bfl[3], bl_b + rel_b[ng][k16]);
                #pragma unroll
                for (int mi = 0; mi < 4; mi++)
                    #pragma unroll
                    for (int rp = 0; rp < 2; rp++) {
                        float* a = acc[mi][ng * 2 + rp];
                        MMA16816(a, afh[mi][0], afh[mi][1], afh[mi][2], afh[mi][3],
                                 bfh[rp * 2], bfh[rp * 2 + 1]);
                        MMA16816(a, afh[mi][0], afh[mi][1], afh[mi][2], afh[mi][3],
                                 bfl[rp * 2], bfl[rp * 2 + 1]);
                        MMA16816(a, afl[mi][0], afl[mi][1], afl[mi][2], afl[mi][3],
                                 bfh[rp * 2], bfh[rp * 2 + 1]);
                    }
            }
        }
    }

    #pragma unroll
    for (int mi = 0; mi < 4; mi++) {
        int row = m0 + warp_m * 64 + mi * 16 + (lid >> 2);
        #pragma unroll
        for (int ni = 0; ni < 8; ni++) {
            int col = n0 + warp_n * 64 + ni * 8 + (lid & 3) * 2;
            *(float2*)&C[(size_t)row * N + col] = make_float2(acc[mi][ni][0], acc[mi][ni][1]);
            *(float2*)&C[(size_t)(row + 8) * N + col] = make_float2(acc[mi][ni][2], acc[mi][ni][3]);
        }
    }
}

// ============ Tensor-core flash attention (causal, GQA, bf16x3) ============
#define ATT_SMEM 131072

__global__ __launch_bounds__(256, 1) void attn_tc_kernel(
    const __nv_bfloat16* __restrict__ Qh, const __nv_bfloat16* __restrict__ Ql,
    const __nv_bfloat16* __restrict__ Kh, const __nv_bfloat16* __restrict__ Kl,
    const __nv_bfloat16* __restrict__ Vh, const __nv_bfloat16* __restrict__ Vl,
    __nv_bfloat16* __restrict__ OutH, __nv_bfloat16* __restrict__ OutL)
{
    extern __shared__ char smem[];
    const uint32_t sb = smem_u32(smem);
    const int tid = threadIdx.x, wid = tid >> 5, lid = tid & 31;
    const int b = blockIdx.z, h = blockIdx.y;
    const int m0 = ((int)gridDim.x - 1 - (int)blockIdx.x) * 128;   // heavy first
    const int kvh = h >> 2;

    #pragma unroll
    for (int i = 0; i < 16; i++) {
        int idx = i * 256 + tid;
        int t = idx >> 11, w = idx & 2047;
        int r = w >> 4, u = w & 15;
        const __nv_bfloat16* src = (t ? Ql : Qh)
            + (size_t)(b * T_SEQ + m0 + r) * 4096 + h * HDIM + u * 8;
        CP_ASYNC16(sb + t * 32768 + OFFA(r, u), src);
    }
    CP_COMMIT();

    auto kvload = [&](int kt, uint32_t base) {
        #pragma unroll
        for (int i = 0; i < 16; i++) {
            int idx = i * 256 + tid;
            int t = idx >> 10, w = idx & 1023;
            int r = w >> 4, u = w & 15;
            const __nv_bfloat16* arr = (t == 0) ? Kh : (t == 1) ? Kl : (t == 2) ? Vh : Vl;
            const __nv_bfloat16* src = arr
                + (size_t)(b * T_SEQ + kt * 64 + r) * 1024 + kvh * HDIM + u * 8;
            CP_ASYNC16(sb + base + t * 16384 + OFFA(r, u), src);
        }
        CP_COMMIT();
    };

    const int nkt = (m0 + 128) / 64;
    kvload(0, 65536);

    CP_WAIT1();
    __syncthreads();

    uint32_t qfh[8][4], qfl[8][4];
    {
        uint32_t r = (uint32_t)(wid * 16 + (lid & 15));
        uint32_t ub = (uint32_t)(lid >> 4);
        #pragma unroll
        for (int ks = 0; ks < 8; ks++) {
            uint32_t off = OFFA(r, ks * 2 + ub);
            LDSM4(qfh[ks][0], qfh[ks][1], qfh[ks][2], qfh[ks][3], sb + off);
            LDSM4(qfl[ks][0], qfl[ks][1], qfl[ks][2], qfl[ks][3], sb + 32768 + off);
        }
    }
    __syncthreads();
    if (nkt > 1) kvload(1, 0);

    float oacc[16][4];
    #pragma unroll
    for (int f = 0; f < 16; f++)
        #pragma unroll
        for (int j = 0; j < 4; j++) oacc[f][j] = 0.f;
    float mr0 = -INFINITY, mr1 = -INFINITY, l0 = 0.f, l1 = 0.f;

    const int row_lo = m0 + wid * 16;
    const int r0 = row_lo + (lid >> 2);

    for (int it = 0; it < nkt; it++) {
        if (it + 1 < nkt) { CP_WAIT1(); } else { CP_WAIT0(); }
        __syncthreads();
        const uint32_t stg = sb + ((it & 1) ? 0u : 65536u);
        const int ktb = it * 64;

        if (ktb <= row_lo + 15) {
            float s[8][4];
            #pragma unroll
            for (int j = 0; j < 8; j++)
                #pragma unroll
                for (int q = 0; q < 4; q++) s[j][q] = 0.f;

            uint32_t br = (uint32_t)((lid & 7) + ((lid >> 4) << 3));
            uint32_t bu = (uint32_t)((lid >> 3) & 1);
            #pragma unroll
            for (int ks = 0; ks < 8; ks++) {
                #pragma unroll
                for (int jj = 0; jj < 4; jj++) {
                    uint32_t kh0, kh1, kh2, kh3, kl0, kl1, kl2, kl3;
                    uint32_t off = OFFA(jj * 16 + br, ks * 2 + bu);
                    LDSM4(kh0, kh1, kh2, kh3, stg + off);
                    LDSM4(kl0, kl1, kl2, kl3, stg + 16384 + off);
                    MMA16816(s[jj * 2],     qfh[ks][0], qfh[ks][1], qfh[ks][2], qfh[ks][3], kh0, kh1);
                    MMA16816(s[jj * 2 + 1], qfh[ks][0], qfh[ks][1], qfh[ks][2], qfh[ks][3], kh2, kh3);
                    MMA16816(s[jj * 2],     qfh[ks][0], qfh[ks][1], qfh[ks][2], qfh[ks][3], kl0, kl1);
                    MMA16816(s[jj * 2 + 1], qfh[ks][0], qfh[ks][1], qfh[ks][2], qfh[ks][3], kl2, kl3);
                    MMA16816(s[jj * 2],     qfl[ks][0], qfl[ks][1], qfl[ks][2], qfl[ks][3], kh0, kh1);
                    MMA16816(s[jj * 2 + 1], qfl[ks][0], qfl[ks][1], qfl[ks][2], qfl[ks][3], kh2, kh3);
                }
            }

            if (ktb + 63 > row_lo) {
                #pragma unroll
                for (int j = 0; j < 8; j++) {
                    int c = ktb + j * 8 + (lid & 3) * 2;
                    if (c > r0)         s[j][0] = -INFINITY;
                    if (c + 1 > r0)     s[j][1] = -INFINITY;
                    if (c > r0 + 8)     s[j][2] = -INFINITY;
                    if (c + 1 > r0 + 8) s[j][3] = -INFINITY;
                }
            }

            float mx0 = -INFINITY, mx1 = -INFINITY;
            #pragma unroll
            for (int j = 0; j < 8; j++) {
                mx0 = fmaxf(mx0, fmaxf(s[j][0], s[j][1]));
                mx1 = fmaxf(mx1, fmaxf(s[j][2], s[j][3]));
            }
            mx0 = fmaxf(mx0, __shfl_xor_sync(0xFFFFFFFFu, mx0, 1));
            mx0 = fmaxf(mx0, __shfl_xor_sync(0xFFFFFFFFu, mx0, 2));
            mx1 = fmaxf(mx1, __shfl_xor_sync(0xFFFFFFFFu, mx1, 1));
            mx1 = fmaxf(mx1, __shfl_xor_sync(0xFFFFFFFFu, mx1, 2));
            float mn0 = fmaxf(mr0, mx0), mn1 = fmaxf(mr1, mx1);
            float c0 = __expf(mr0 - mn0), c1 = __expf(mr1 - mn1);
            mr0 = mn0; mr1 = mn1;
            float rs0 = 0.f, rs1 = 0.f;
            #pragma unroll
            for (int j = 0; j < 8; j++) {
                s[j][0] = __expf(s[j][0] - mn0);
                s[j][1] = __expf(s[j][1] - mn0);
                s[j][2] = __expf(s[j][2] - mn1);
                s[j][3] = __expf(s[j][3] - mn1);
                rs0 += s[j][0] + s[j][1];
                rs1 += s[j][2] + s[j][3];
            }
            rs0 += __shfl_xor_sync(0xFFFFFFFFu, rs0, 1);
            rs0 += __shfl_xor_sync(0xFFFFFFFFu, rs0, 2);
            rs1 += __shfl_xor_sync(0xFFFFFFFFu, rs1, 1);
            rs1 += __shfl_xor_sync(0xFFFFFFFFu, rs1, 2);
            l0 = l0 * c0 + rs0;
            l1 = l1 * c1 + rs1;
            #pragma unroll
            for (int f = 0; f < 16; f++) {
                oacc[f][0] *= c0; oacc[f][1] *= c0;
                oacc[f][2] *= c1; oacc[f][3] *= c1;
            }

            #pragma unroll
            for (int ks2 = 0; ks2 < 4; ks2++) {
                int j0 = ks2 * 2, j1 = j0 + 1;
                uint32_t pah[4], pal[4];
                pack_hl(s[j0][0], s[j0][1], pah[0], pal[0]);
                pack_hl(s[j0][2], s[j0][3], pah[1], pal[1]);
                pack_hl(s[j1][0], s[j1][1], pah[2], pal[2]);
                pack_hl(s[j1][2], s[j1][3], pah[3], pal[3]);
                uint32_t vr = (uint32_t)(ks2 * 16 + (lid & 15));
                uint32_t vub = (uint32_t)(lid >> 4);
                #pragma unroll
                for (int ng = 0; ng < 8; ng++) {
                    uint32_t vh0, vh1, vh2, vh3, vl0, vl1, vl2, vl3;
                    uint32_t off = OFFA(vr, ng * 2 + vub);
                    LDSM4T(vh0, vh1, vh2, vh3, stg + 32768 + off);
                    LDSM4T(vl0, vl1, vl2, vl3, stg + 49152 + off);
                    MMA16816(oacc[ng * 2],     pah[0], pah[1], pah[2], pah[3], vh0, vh1);
                    MMA16816(oacc[ng * 2 + 1], pah[0], pah[1], pah[2], pah[3], vh2, vh3);
                    MMA16816(oacc[ng * 2],     pah[0], pah[1], pah[2], pah[3], vl0, vl1);
                    MMA16816(oacc[ng * 2 + 1], pah[0], pah[1], pah[2], pah[3], vl2, vl3);
                    MMA16816(oacc[ng * 2],     pal[0], pal[1], pal[2], pal[3], vh0, vh1);
                    MMA16816(oacc[ng * 2 + 1], pal[0], pal[1], pal[2], pal[3], vh2, vh3);
                }
            }
        }
        __syncthreads();
        if (it + 2 < nkt) kvload(it + 2, (it & 1) ? 0u : 65536u);
    }

    float inv0 = 1.f / l0, inv1 = 1.f / l1;
    size_t grow = (size_t)(b * T_SEQ + r0);
    #pragma unroll
    for (int f = 0; f < 16; f++) {
        int col = h * HDIM + f * 8 + (lid & 3) * 2;
        uint32_t hh, ll;
        pack_hl(oacc[f][0] * inv0, oacc[f][1] * inv0, hh, ll);
        *(uint32_t*)(OutH + grow * 4096 + col) = hh;
        *(uint32_t*)(OutL + grow * 4096 + col) = ll;
        pack_hl(oacc[f][2] * inv1, oacc[f][3] * inv1, hh, ll);
        *(uint32_t*)(OutH + (grow + 8) * 4096 + col) = hh;
        *(uint32_t*)(OutL + (grow + 8) * 4096 + col) = ll;
    }
}

// ================= launcher =================
extern "C" void kernel_launch(void* const* d_in, const int* in_sizes, int n_in,
                              void* d_out, int out_size)
{
    const float* x  = (const float*)d_in[0];
    const float* wq = (const float*)d_in[1];
    const float* wk = (const float*)d_in[2];
    const float* wv = (const float*)d_in[3];
    const float* wo = (const float*)d_in[4];
    const int*   sp = (n_in > 5) ? (const int*)d_in[5] : nullptr;
    float* out = (float*)d_out;
    (void)in_sizes; (void)out_size;

    float* gqkv;
    cudaGetSymbolAddress((void**)&gqkv, g_qkv);
    __nv_bfloat16 *xh, *xl, *ah, *al, *qh, *ql, *kh, *kl, *vh, *vl;
    __nv_bfloat16 *wqkvh, *wqkvl, *woh, *wol;
    float4* tab;
    cudaGetSymbolAddress((void**)&xh, g_xh);       cudaGetSymbolAddress((void**)&xl, g_xl);
    cudaGetSymbolAddress((void**)&ah, g_ah);       cudaGetSymbolAddress((void**)&al, g_al);
    cudaGetSymbolAddress((void**)&qh, g_qh);       cudaGetSymbolAddress((void**)&ql, g_ql);
    cudaGetSymbolAddress((void**)&kh, g_kh);       cudaGetSymbolAddress((void**)&kl, g_kl);
    cudaGetSymbolAddress((void**)&vh, g_vh);       cudaGetSymbolAddress((void**)&vl, g_vl);
    cudaGetSymbolAddress((void**)&wqkvh, g_wqkvh); cudaGetSymbolAddress((void**)&wqkvl, g_wqkvl);
    cudaGetSymbolAddress((void**)&woh, g_woh);     cudaGetSymbolAddress((void**)&wol, g_wol);
    cudaGetSymbolAddress((void**)&tab, g_ropetab);

    cudaFuncSetAttribute(gemm3_big_kernel, cudaFuncAttributeMaxDynamicSharedMemorySize, BIG_SMEM);
    cudaFuncSetAttribute(attn_tc_kernel, cudaFuncAttributeMaxDynamicSharedMemorySize, ATT_SMEM);

    int n4x = BT * 4096 / 4;

    split_kernel<<<n4x / 256, 256>>>(x, xh, xl, n4x);
    ropetab_kernel<<<(1024 * 64) / 256, 256>>>(sp, tab);
    // weights -> one concatenated [6144][4096] bf16 hi/lo buffer
    tsplit2_kernel<<<dim3(4096 / 32, 4096 / 64), 256>>>(wq, wqkvh, wqkvl, 4096, 4096);
    tsplit2_kernel<<<dim3(1024 / 32, 4096 / 64), 256>>>(wk, wqkvh + (size_t)4096 * 4096,
                                                        wqkvl + (size_t)4096 * 4096, 4096, 1024);
    tsplit2_kernel<<<dim3(1024 / 32, 4096 / 64), 256>>>(wv, wqkvh + (size_t)5120 * 4096,
                                                        wqkvl + (size_t)5120 * 4096, 4096, 1024);
    tsplit2_kernel<<<dim3(4096 / 32, 4096 / 64), 256>>>(wo, woh, wol, 4096, 4096);

    // fused Q|K|V projection: C[2048, 6144]
    gemm3_big_kernel<<<dim3(6144 / 256, BT / 128), 256, BIG_SMEM>>>(
        xh, xl, wqkvh, wqkvl, gqkv, BT, 6144, 4096);

    // RoPE (table) + bf16 hi/lo split; scale baked into q
    rope_split_kernel<<<(BT * 2048) / 256, 256>>>(gqkv, 6144, qh, ql, 4096,
                                                  BT * 2048, tab, 0.08838834764831845f);
    rope_split_kernel<<<(BT * 512) / 256, 256>>>(gqkv + 4096, 6144, kh, kl, 1024,
                                                 BT * 512, tab, 1.0f);
    splitstride_kernel<<<(BT * 256) / 256, 256>>>(gqkv + 5120, 1536, 256, vh, vl, BT * 256);

    // tensor-core flash attention (emits bf16 hi/lo directly)
    attn_tc_kernel<<<dim3(T_SEQ / 128, NH, B_SZ), 256, ATT_SMEM>>>(qh, ql, kh, kl, vh, vl, ah, al);

    // output projection
    gemm3_big_kernel<<<dim3(4096 / 256, BT / 128), 256, BIG_SMEM>>>(
        ah, al, woh, wol, out, BT, 4096, 4096);
}

// round 15
// speedup vs baseline: 1.5068x; 1.5068x over previous
#include <cuda_runtime.h>
#include <cuda_bf16.h>
#include <math.h>
#include <stdint.h>

#define B_SZ   2
#define T_SEQ  1024
#define BT     2048
#define NH     32
#define HDIM   128

// ================= scratch =================
__device__ float g_q[BT * 4096];
__device__ float g_kv[BT * 2048];
__device__ __nv_bfloat16 g_xh[BT * 4096], g_xl[BT * 4096];
__device__ __nv_bfloat16 g_ah[BT * 4096], g_al[BT * 4096];
__device__ __nv_bfloat16 g_qh[BT * 4096], g_ql[BT * 4096];
__device__ __nv_bfloat16 g_kh[BT * 1024], g_kl[BT * 1024];
__device__ __nv_bfloat16 g_vh[BT * 1024], g_vl[BT * 1024];
__device__ __nv_bfloat16 g_wqh[4096 * 4096], g_wql[4096 * 4096];
__device__ __nv_bfloat16 g_wkvh[2048 * 4096], g_wkvl[2048 * 4096];
__device__ __nv_bfloat16 g_woh[4096 * 4096], g_wol[4096 * 4096];
__device__ float4 g_ropetab[1024 * 64];

// ================= helpers =================
__device__ __forceinline__ uint32_t smem_u32(const void* p) {
    uint32_t a;
    asm("{ .reg .u64 t; cvta.to.shared.u64 t, %1; cvt.u32.u64 %0, t; }"
        : "=r"(a) : "l"(p));
    return a;
}
// GEMM tile swizzle: (rows)x32(k) bf16 tile
__device__ __forceinline__ uint32_t swz(uint32_t r, uint32_t u) {
    return ((r >> 1) << 7) | (((((r & 1) << 2) | u) ^ ((r >> 1) & 7)) << 4);
}
// attention tile swizzle: (rows)x128 bf16 tile, 16 16B-units/row
#define OFFA(r, u) (((uint32_t)(r)) * 256 + ((((uint32_t)(u)) ^ (((uint32_t)(r)) & 7)) << 4))

#define CP_ASYNC16(dst, src) \
    asm volatile("cp.async.cg.shared.global [%0], [%1], 16;" :: "r"(dst), "l"(src))
#define CP_COMMIT() asm volatile("cp.async.commit_group;" ::: "memory")
#define CP_WAIT0()  asm volatile("cp.async.wait_group 0;" ::: "memory")
#define CP_WAIT1()  asm volatile("cp.async.wait_group 1;" ::: "memory")
#define CP_WAIT2()  asm volatile("cp.async.wait_group 2;" ::: "memory")

#define LDSM4(r0, r1, r2, r3, a) \
    asm volatile("ldmatrix.sync.aligned.m8n8.x4.shared.b16 {%0,%1,%2,%3}, [%4];" \
        : "=r"(r0), "=r"(r1), "=r"(r2), "=r"(r3) : "r"(a))
#define LDSM4T(r0, r1, r2, r3, a) \
    asm volatile("ldmatrix.sync.aligned.m8n8.x4.trans.shared.b16 {%0,%1,%2,%3}, [%4];" \
        : "=r"(r0), "=r"(r1), "=r"(r2), "=r"(r3) : "r"(a))

#define MMA16816(c, a0, a1, a2, a3, b0, b1) \
    asm volatile("mma.sync.aligned.m16n8k16.row.col.f32.bf16.bf16.f32 " \
        "{%0,%1,%2,%3}, {%4,%5,%6,%7}, {%8,%9}, {%0,%1,%2,%3};" \
        : "+f"((c)[0]), "+f"((c)[1]), "+f"((c)[2]), "+f"((c)[3]) \
        : "r"(a0), "r"(a1), "r"(a2), "r"(a3), "r"(b0), "r"(b1))

__device__ __forceinline__ void pack_hl(float f0, float f1, uint32_t& h, uint32_t& l) {
    __nv_bfloat162 hh = __floats2bfloat162_rn(f0, f1);
    float r0 = f0 - __bfloat162float(hh.x);
    float r1 = f1 - __bfloat162float(hh.y);
    __nv_bfloat162 ll = __floats2bfloat162_rn(r0, r1);
    h = *(uint32_t*)&hh;
    l = *(uint32_t*)&ll;
}

// ============ rope table: tab[t][p] = (cos a0, sin a0, cos a1, sin a1) ============
__global__ void ropetab_kernel(const int* __restrict__ sp, float4* __restrict__ tab)
{
    int i = blockIdx.x * blockDim.x + threadIdx.x;   // 0..65535
    int t = i >> 6, p = i & 63;
    int start = (sp == nullptr) ? 0 : *sp;
    float tt = (float)(start + t);
    const float lf = 9.210340371976184f;
    int j0 = (2 * p) & 63;
    float a0 = tt * expf(-(float)j0       * (lf / 64.f));
    float a1 = tt * expf(-(float)(j0 + 1) * (lf / 64.f));
    float c0, s0, c1, s1;
    sincosf(a0, &s0, &c0);
    sincosf(a1, &s1, &c1);
    tab[i] = make_float4(c0, s0, c1, s1);
}

// ============ split fp32 -> bf16 hi/lo (row-major dense) ============
__global__ void split_kernel(const float* __restrict__ in,
                             __nv_bfloat16* __restrict__ hi,
                             __nv_bfloat16* __restrict__ lo, int n4)
{
    int i = blockIdx.x * blockDim.x + threadIdx.x;
    if (i >= n4) return;
    float4 v = ((const float4*)in)[i];
    __nv_bfloat16 h0 = __float2bfloat16(v.x);
    __nv_bfloat16 h1 = __float2bfloat16(v.y);
    __nv_bfloat16 h2 = __float2bfloat16(v.z);
    __nv_bfloat16 h3 = __float2bfloat16(v.w);
    __nv_bfloat162* hp = (__nv_bfloat162*)hi;
    __nv_bfloat162* lp = (__nv_bfloat162*)lo;
    hp[2 * i]     = __nv_bfloat162(h0, h1);
    hp[2 * i + 1] = __nv_bfloat162(h2, h3);
    lp[2 * i]     = __nv_bfloat162(__float2bfloat16(v.x - __bfloat162float(h0)),
                                   __float2bfloat16(v.y - __bfloat162float(h1)));
    lp[2 * i + 1] = __nv_bfloat162(__float2bfloat16(v.z - __bfloat162float(h2)),
                                   __float2bfloat16(v.w - __bfloat162float(h3)));
}

// ============ strided split: in[row*in_stride4 + c4] (float4 units) ============
__global__ void splitstride_kernel(const float* __restrict__ in, int in_stride4,
                                   int cols4, __nv_bfloat16* __restrict__ hi,
                                   __nv_bfloat16* __restrict__ lo, int n4)
{
    int i = blockIdx.x * blockDim.x + threadIdx.x;
    if (i >= n4) return;
    int row = i / cols4;
    int c4 = i - row * cols4;
    float4 v = ((const float4*)in)[row * in_stride4 + c4];
    int o = row * cols4 + c4;
    __nv_bfloat16 h0 = __float2bfloat16(v.x);
    __nv_bfloat16 h1 = __float2bfloat16(v.y);
    __nv_bfloat16 h2 = __float2bfloat16(v.z);
    __nv_bfloat16 h3 = __float2bfloat16(v.w);
    __nv_bfloat162* hp = (__nv_bfloat162*)hi;
    __nv_bfloat162* lp = (__nv_bfloat162*)lo;
    hp[2 * o]     = __nv_bfloat162(h0, h1);
    hp[2 * o + 1] = __nv_bfloat162(h2, h3);
    lp[2 * o]     = __nv_bfloat162(__float2bfloat16(v.x - __bfloat162float(h0)),
                                   __float2bfloat16(v.y - __bfloat162float(h1)));
    lp[2 * o + 1] = __nv_bfloat162(__float2bfloat16(v.z - __bfloat162float(h2)),
                                   __float2bfloat16(v.w - __bfloat162float(h3)));
}

// ============ transpose + split v2: W[K][N] fp32 -> Wt[N][K] bf16 hi/lo ============
__global__ __launch_bounds__(256) void tsplit2_kernel(
    const float* __restrict__ W, __nv_bfloat16* __restrict__ hi,
    __nv_bfloat16* __restrict__ lo, int K, int N)
{
    __shared__ float s[32][66];    // [n][k], pad 2 keeps float2 8B-aligned
    const int n0 = blockIdx.x * 32, k0 = blockIdx.y * 64;
    const int tid = threadIdx.x;
    #pragma unroll
    for (int i = 0; i < 8; i++) {
        int idx = tid + i * 256;
        int r = idx >> 5;          // k-rel 0..63
        int c = idx & 31;          // n-rel
        s[c][r] = W[(size_t)(k0 + r) * N + n0 + c];
    }
    __syncthreads();
    #pragma unroll
    for (int i = 0; i < 4; i++) {
        int p = tid + i * 256;
        int row = p >> 5;          // n-rel 0..31
        int pr = p & 31;           // k-pair 0..31
        float2 v = *(float2*)&s[row][pr * 2];
        __nv_bfloat16 h0 = __float2bfloat16(v.x);
        __nv_bfloat16 h1 = __float2bfloat16(v.y);
        __nv_bfloat162 hh(h0, h1);
        __nv_bfloat162 ll(__float2bfloat16(v.x - __bfloat162float(h0)),
                          __float2bfloat16(v.y - __bfloat162float(h1)));
        size_t o = (size_t)(n0 + row) * K + k0 + pr * 2;
        *(uint32_t*)(hi + o) = *(uint32_t*)&hh;
        *(uint32_t*)(lo + o) = *(uint32_t*)&ll;
    }
}

// ============ RoPE (table) + split (strided in/out) ============
__global__ void rope_split_kernel(const float* __restrict__ in, int in_stride,
                                  __nv_bfloat16* __restrict__ hi,
                                  __nv_bfloat16* __restrict__ lo, int out_stride,
                                  int total_pairs, const float4* __restrict__ tab,
                                  float scale)
{
    int idx = blockIdx.x * blockDim.x + threadIdx.x;
    if (idx >= total_pairs) return;
    int halfout = out_stride >> 1;
    int row = idx / halfout;
    int p   = idx - row * halfout;
    int c0  = p * 2;
    int pp  = (c0 & (HDIM - 1)) >> 1;
    float4 cs = tab[(row & (T_SEQ - 1)) * 64 + pp];
    const float* base = in + (size_t)row * in_stride + c0;
    float x0 = base[0], x1 = base[1];
    float y0 = (x0 * cs.x - x1 * cs.y) * scale;
    float y1 = (x1 * cs.z + x0 * cs.w) * scale;
    uint32_t h, l;
    pack_hl(y0, y1, h, l);
    *(uint32_t*)(hi + (size_t)row * out_stride + c0) = h;
    *(uint32_t*)(lo + (size_t)row * out_stride + c0) = l;
}

// ============ bf16x3 GEMM 128x128: C = A @ Bt^T ============
#define KC      32
#define NSTAGE  3
#define TILE_B  8192
#define STAGE_B (4 * TILE_B)
#define GEMM_SMEM (NSTAGE * STAGE_B)

__global__ __launch_bounds__(256, 1) void gemm3_kernel(
    const __nv_bfloat16* __restrict__ Ah, const __nv_bfloat16* __restrict__ Al,
    const __nv_bfloat16* __restrict__ Bh, const __nv_bfloat16* __restrict__ Bl,
    float* __restrict__ C, int M, int N, int K)
{
    extern __shared__ char smem[];
    const uint32_t sb = smem_u32(smem);
    const int tid = threadIdx.x, wid = tid >> 5, lid = tid & 31;
    const int m0 = blockIdx.y * 128, n0 = blockIdx.x * 128;
    const int warp_m = wid & 1, warp_n = wid >> 1;
    const int NCH = K / KC;

    uint32_t rel_a[4][2], rel_b[2][2];
    {
        uint32_t ar = (uint32_t)(warp_m * 64 + (lid & 15));
        uint32_t au = (uint32_t)(lid >> 4);
        #pragma unroll
        for (int mi = 0; mi < 4; mi++)
            #pragma unroll
            for (int k16 = 0; k16 < 2; k16++)
                rel_a[mi][k16] = swz(ar + mi * 16, au + k16 * 2);
        uint32_t br = (uint32_t)(warp_n * 32 + (lid & 7) + ((lid >> 4) << 3));
        uint32_t bu = (uint32_t)((lid >> 3) & 1);
        #pragma unroll
        for (int ng = 0; ng < 2; ng++)
            #pragma unroll
            for (int k16 = 0; k16 < 2; k16++)
                rel_b[ng][k16] = swz(br + ng * 16, bu + k16 * 2);
    }

    float acc[4][4][4];
    #pragma unroll
    for (int mi = 0; mi < 4; mi++)
        #pragma unroll
        for (int ni = 0; ni < 4; ni++)
            #pragma unroll
            for (int j = 0; j < 4; j++) acc[mi][ni][j] = 0.f;

    auto load_stage = [&](int s, int chunk) {
        const int k0 = chunk * KC;
        const uint32_t st = sb + s * STAGE_B;
        #pragma unroll
        for (int t = 0; t < 8; t++) {
            int g = t * 256 + tid;
            int tile = g >> 9;
            int w = g & 511;
            int r = w >> 2, u = w & 3;
            uint32_t dst = st + tile * TILE_B + swz(r, u);
            const __nv_bfloat16* src;
            if (tile == 0)      src = Ah + (size_t)(m0 + r) * K + k0 + u * 8;
            else if (tile == 1) src = Al + (size_t)(m0 + r) * K + k0 + u * 8;
            else if (tile == 2) src = Bh + (size_t)(n0 + r) * K + k0 + u * 8;
            else                src = Bl + (size_t)(n0 + r) * K + k0 + u * 8;
            CP_ASYNC16(dst, src);
        }
    };

    load_stage(0, 0); CP_COMMIT();
    load_stage(1, 1); CP_COMMIT();

    for (int i = 0; i < NCH; i++) {
        CP_WAIT1();
        __syncthreads();
        int nxt = i + NSTAGE - 1;
        if (nxt < NCH) load_stage(nxt % NSTAGE, nxt);
        CP_COMMIT();

        const uint32_t st = sb + (i % NSTAGE) * STAGE_B;
        const uint32_t ah_b = st, al_b = st + TILE_B;
        const uint32_t bh_b = st + 2 * TILE_B, bl_b = st + 3 * TILE_B;

        #pragma unroll
        for (int k16 = 0; k16 < 2; k16++) {
            uint32_t afh[4][4], afl[4][4], bfh[2][4], bfl[2][4];
            #pragma unroll
            for (int mi = 0; mi < 4; mi++) {
                LDSM4(afh[mi][0], afh[mi][1], afh[mi][2], afh[mi][3], ah_b + rel_a[mi][k16]);
                LDSM4(afl[mi][0], afl[mi][1], afl[mi][2], afl[mi][3], al_b + rel_a[mi][k16]);
            }
            #pragma unroll
            for (int ng = 0; ng < 2; ng++) {
                LDSM4(bfh[ng][0], bfh[ng][1], bfh[ng][2], bfh[ng][3], bh_b + rel_b[ng][k16]);
                LDSM4(bfl[ng][0], bfl[ng][1], bfl[ng][2], bfl[ng][3], bl_b + rel_b[ng][k16]);
            }
            #pragma unroll
            for (int mi = 0; mi < 4; mi++)
                #pragma unroll
                for (int ni = 0; ni < 4; ni++) {
                    int ng = ni >> 1, rp = (ni & 1) * 2;
                    MMA16816(acc[mi][ni], afh[mi][0], afh[mi][1], afh[mi][2], afh[mi][3],
                             bfh[ng][rp], bfh[ng][rp + 1]);
                    MMA16816(acc[mi][ni], afh[mi][0], afh[mi][1], afh[mi][2], afh[mi][3],
                             bfl[ng][rp], bfl[ng][rp + 1]);
                    MMA16816(acc[mi][ni], afl[mi][0], afl[mi][1], afl[mi][2], afl[mi][3],
                             bfh[ng][rp], bfh[ng][rp + 1]);
                }
        }
    }

    #pragma unroll
    for (int mi = 0; mi < 4; mi++) {
        int row = m0 + warp_m * 64 + mi * 16 + (lid >> 2);
        #pragma unroll
        for (int ni = 0; ni < 4; ni++) {
            int col = n0 + warp_n * 32 + ni * 8 + (lid & 3) * 2;
            *(float2*)&C[(size_t)row * N + col] = make_float2(acc[mi][ni][0], acc[mi][ni][1]);
            *(float2*)&C[(size_t)(row + 8) * N + col] = make_float2(acc[mi][ni][2], acc[mi][ni][3]);
        }
    }
}

// ============ bf16x3 GEMM 128x256 (for Q/O) ============
#define NSTB    4
#define A_TB    8192
#define B_TB    16384
#define STAGE_BB (2 * A_TB + 2 * B_TB)
#define BIG_SMEM (NSTB * STAGE_BB)

__global__ __launch_bounds__(256, 1) void gemm3_big_kernel(
    const __nv_bfloat16* __restrict__ Ah, const __nv_bfloat16* __restrict__ Al,
    const __nv_bfloat16* __restrict__ Bh, const __nv_bfloat16* __restrict__ Bl,
    float* __restrict__ C, int M, int N, int K)
{
    extern __shared__ char smem[];
    const uint32_t sb = smem_u32(smem);
    const int tid = threadIdx.x, wid = tid >> 5, lid = tid & 31;
    const int m0 = blockIdx.y * 128, n0 = blockIdx.x * 256;
    const int warp_m = wid & 1, warp_n = wid >> 1;
    const int NCH = K / KC;

    uint32_t rel_a[4][2], rel_b[4][2];
    {
        uint32_t ar = (uint32_t)(warp_m * 64 + (lid & 15));
        uint32_t au = (uint32_t)(lid >> 4);
        #pragma unroll
        for (int mi = 0; mi < 4; mi++)
            #pragma unroll
            for (int k16 = 0; k16 < 2; k16++)
                rel_a[mi][k16] = swz(ar + mi * 16, au + k16 * 2);
        uint32_t br = (uint32_t)(warp_n * 64 + (lid & 7) + ((lid >> 4) << 3));
        uint32_t bu = (uint32_t)((lid >> 3) & 1);
        #pragma unroll
        for (int ng = 0; ng < 4; ng++)
            #pragma unroll
            for (int k16 = 0; k16 < 2; k16++)
                rel_b[ng][k16] = swz(br + ng * 16, bu + k16 * 2);
    }

    float acc[4][8][4];
    #pragma unroll
    for (int mi = 0; mi < 4; mi++)
        #pragma unroll
        for (int ni = 0; ni < 8; ni++)
            #pragma unroll
            for (int j = 0; j < 4; j++) acc[mi][ni][j] = 0.f;

    auto load_stage = [&](int s, int chunk) {
        const int k0 = chunk * KC;
        const uint32_t st = sb + s * STAGE_BB;
        #pragma unroll
        for (int t = 0; t < 12; t++) {
            int g = t * 256 + tid;
            uint32_t dst;
            const __nv_bfloat16* src;
            if (g < 1024) {
                int r = (g & 511) >> 2, u = g & 3;
                dst = st + (g >> 9) * A_TB + swz(r, u);
                src = ((g >> 9) ? Al : Ah) + (size_t)(m0 + r) * K + k0 + u * 8;
            } else {
                int w = g - 1024;
                int r = (w & 1023) >> 2, u = w & 3;
                dst = st + 2 * A_TB + (w >> 10) * B_TB + swz(r, u);
                src = ((w >> 10) ? Bl : Bh) + (size_t)(n0 + r) * K + k0 + u * 8;
            }
            CP_ASYNC16(dst, src);
        }
    };

    load_stage(0, 0); CP_COMMIT();
    load_stage(1, 1); CP_COMMIT();
    load_stage(2, 2); CP_COMMIT();

    for (int i = 0; i < NCH; i++) {
        CP_WAIT2();
        __syncthreads();
        int nxt = i + NSTB - 1;
        if (nxt < NCH) load_stage(nxt % NSTB, nxt);
        CP_COMMIT();

        const uint32_t st = sb + (i % NSTB) * STAGE_BB;
        const uint32_t ah_b = st, al_b = st + A_TB;
        const uint32_t bh_b = st + 2 * A_TB, bl_b = st + 2 * A_TB + B_TB;

        #pragma unroll
        for (int k16 = 0; k16 < 2; k16++) {
            uint32_t afh[4][4], afl[4][4];
            #pragma unroll
            for (int mi = 0; mi < 4; mi++) {
                LDSM4(afh[mi][0], afh[mi][1], afh[mi][2], afh[mi][3], ah_b + rel_a[mi][k16]);
                LDSM4(afl[mi][0], afl[mi][1], afl[mi][2], afl[mi][3], al_b + rel_a[mi][k16]);
            }
            #pragma unroll
            for (int ng = 0; ng < 4; ng++) {
                uint32_t bfh[4], bfl[4];
                LDSM4(bfh[0], bfh[1], bfh[2], bfh[3], bh_b + rel_b[ng][k16]);
                LDSM4(bfl[0], bfl[1], bfl[2], bfl[3], bl_b + rel_b[ng][k16]);
                #pragma unroll
                for (int mi = 0; mi < 4; mi++)
                    #pragma unroll
                    for (int rp = 0; rp < 2; rp++) {
                        float* a = acc[mi][ng * 2 + rp];
                        MMA16816(a, afh[mi][0], afh[mi][1], afh[mi][2], afh[mi][3],
                                 bfh[rp * 2], bfh[rp * 2 + 1]);
                        MMA16816(a, afh[mi][0], afh[mi][1], afh[mi][2], afh[mi][3],
                                 bfl[rp * 2], bfl[rp * 2 + 1]);
                        MMA16816(a, afl[mi][0], afl[mi][1], afl[mi][2], afl[mi][3],
                                 bfh[rp * 2], bfh[rp * 2 + 1]);
                    }
            }
        }
    }

    #pragma unroll
    for (int mi = 0; mi < 4; mi++) {
        int row = m0 + warp_m * 64 + mi * 16 + (lid >> 2);
        #pragma unroll
        for (int ni = 0; ni < 8; ni++) {
            int col = n0 + warp_n * 64 + ni * 8 + (lid & 3) * 2;
            *(float2*)&C[(size_t)row * N + col] = make_float2(acc[mi][ni][0], acc[mi][ni][1]);
            *(float2*)&C[(size_t)(row + 8) * N + col] = make_float2(acc[mi][ni][2], acc[mi][ni][3]);
        }
    }
}

// ============ Tensor-core flash attention (causal, GQA, bf16x3) ============
#define ATT_SMEM 131072

__global__ __launch_bounds__(256, 1) void attn_tc_kernel(
    const __nv_bfloat16* __restrict__ Qh, const __nv_bfloat16* __restrict__ Ql,
    const __nv_bfloat16* __restrict__ Kh, const __nv_bfloat16* __restrict__ Kl,
    const __nv_bfloat16* __restrict__ Vh, const __nv_bfloat16* __restrict__ Vl,
    __nv_bfloat16* __restrict__ OutH, __nv_bfloat16* __restrict__ OutL)
{
    extern __shared__ char smem[];
    const uint32_t sb = smem_u32(smem);
    const int tid = threadIdx.x, wid = tid >> 5, lid = tid & 31;
    const int b = blockIdx.z, h = blockIdx.y;
    const int m0 = ((int)gridDim.x - 1 - (int)blockIdx.x) * 128;   // heavy first
    const int kvh = h >> 2;

    #pragma unroll
    for (int i = 0; i < 16; i++) {
        int idx = i * 256 + tid;
        int t = idx >> 11, w = idx & 2047;
        int r = w >> 4, u = w & 15;
        const __nv_bfloat16* src = (t ? Ql : Qh)
            + (size_t)(b * T_SEQ + m0 + r) * 4096 + h * HDIM + u * 8;
        CP_ASYNC16(sb + t * 32768 + OFFA(r, u), src);
    }
    CP_COMMIT();

    auto kvload = [&](int kt, uint32_t base) {
        #pragma unroll
        for (int i = 0; i < 16; i++) {
            int idx = i * 256 + tid;
            int t = idx >> 10, w = idx & 1023;
            int r = w >> 4, u = w & 15;
            const __nv_bfloat16* arr = (t == 0) ? Kh : (t == 1) ? Kl : (t == 2) ? Vh : Vl;
            const __nv_bfloat16* src = arr
                + (size_t)(b * T_SEQ + kt * 64 + r) * 1024 + kvh * HDIM + u * 8;
            CP_ASYNC16(sb + base + t * 16384 + OFFA(r, u), src);
        }
        CP_COMMIT();
    };

    const int nkt = (m0 + 128) / 64;
    kvload(0, 65536);

    CP_WAIT1();
    __syncthreads();

    uint32_t qfh[8][4], qfl[8][4];
    {
        uint32_t r = (uint32_t)(wid * 16 + (lid & 15));
        uint32_t ub = (uint32_t)(lid >> 4);
        #pragma unroll
        for (int ks = 0; ks < 8; ks++) {
            uint32_t off = OFFA(r, ks * 2 + ub);
            LDSM4(qfh[ks][0], qfh[ks][1], qfh[ks][2], qfh[ks][3], sb + off);
            LDSM4(qfl[ks][0], qfl[ks][1], qfl[ks][2], qfl[ks][3], sb + 32768 + off);
        }
    }
    __syncthreads();
    if (nkt > 1) kvload(1, 0);

    float oacc[16][4];
    #pragma unroll
    for (int f = 0; f < 16; f++)
        #pragma unroll
        for (int j = 0; j < 4; j++) oacc[f][j] = 0.f;
    float mr0 = -INFINITY, mr1 = -INFINITY, l0 = 0.f, l1 = 0.f;

    const int row_lo = m0 + wid * 16;
    const int r0 = row_lo + (lid >> 2);

    for (int it = 0; it < nkt; it++) {
        if (it + 1 < nkt) { CP_WAIT1(); } else { CP_WAIT0(); }
        __syncthreads();
        const uint32_t stg = sb + ((it & 1) ? 0u : 65536u);
        const int ktb = it * 64;

        if (ktb <= row_lo + 15) {
            float s[8][4];
            #pragma unroll
            for (int j = 0; j < 8; j++)
                #pragma unroll
                for (int q = 0; q < 4; q++) s[j][q] = 0.f;

            uint32_t br = (uint32_t)((lid & 7) + ((lid >> 4) << 3));
            uint32_t bu = (uint32_t)((lid >> 3) & 1);
            #pragma unroll
            for (int ks = 0; ks < 8; ks++) {
                #pragma unroll
                for (int jj = 0; jj < 4; jj++) {
                    uint32_t kh0, kh1, kh2, kh3, kl0, kl1, kl2, kl3;
                    uint32_t off = OFFA(jj * 16 + br, ks * 2 + bu);
                    LDSM4(kh0, kh1, kh2, kh3, stg + off);
                    LDSM4(kl0, kl1, kl2, kl3, stg + 16384 + off);
                    MMA16816(s[jj * 2],     qfh[ks][0], qfh[ks][1], qfh[ks][2], qfh[ks][3], kh0, kh1);
                    MMA16816(s[jj * 2 + 1], qfh[ks][0], qfh[ks][1], qfh[ks][2], qfh[ks][3], kh2, kh3);
                    MMA16816(s[jj * 2],     qfh[ks][0], qfh[ks][1], qfh[ks][2], qfh[ks][3], kl0, kl1);
                    MMA16816(s[jj * 2 + 1], qfh[ks][0], qfh[ks][1], qfh[ks][2], qfh[ks][3], kl2, kl3);
                    MMA16816(s[jj * 2],     qfl[ks][0], qfl[ks][1], qfl[ks][2], qfl[ks][3], kh0, kh1);
                    MMA16816(s[jj * 2 + 1], qfl[ks][0], qfl[ks][1], qfl[ks][2], qfl[ks][3], kh2, kh3);
                }
            }

            if (ktb + 63 > row_lo) {
                #pragma unroll
                for (int j = 0; j < 8; j++) {
                    int c = ktb + j * 8 + (lid & 3) * 2;
                    if (c > r0)         s[j][0] = -INFINITY;
                    if (c + 1 > r0)     s[j][1] = -INFINITY;
                    if (c > r0 + 8)     s[j][2] = -INFINITY;
                    if (c + 1 > r0 + 8) s[j][3] = -INFINITY;
                }
            }

            float mx0 = -INFINITY, mx1 = -INFINITY;
            #pragma unroll
            for (int j = 0; j < 8; j++) {
                mx0 = fmaxf(mx0, fmaxf(s[j][0], s[j][1]));
                mx1 = fmaxf(mx1, fmaxf(s[j][2], s[j][3]));
            }
            mx0 = fmaxf(mx0, __shfl_xor_sync(0xFFFFFFFFu, mx0, 1));
            mx0 = fmaxf(mx0, __shfl_xor_sync(0xFFFFFFFFu, mx0, 2));
            mx1 = fmaxf(mx1, __shfl_xor_sync(0xFFFFFFFFu, mx1, 1));
            mx1 = fmaxf(mx1, __shfl_xor_sync(0xFFFFFFFFu, mx1, 2));
            float mn0 = fmaxf(mr0, mx0), mn1 = fmaxf(mr1, mx1);
            float c0 = __expf(mr0 - mn0), c1 = __expf(mr1 - mn1);
            mr0 = mn0; mr1 = mn1;
            float rs0 = 0.f, rs1 = 0.f;
            #pragma unroll
            for (int j = 0; j < 8; j++) {
                s[j][0] = __expf(s[j][0] - mn0);
                s[j][1] = __expf(s[j][1] - mn0);
                s[j][2] = __expf(s[j][2] - mn1);
                s[j][3] = __expf(s[j][3] - mn1);
                rs0 += s[j][0] + s[j][1];
                rs1 += s[j][2] + s[j][3];
            }
            rs0 += __shfl_xor_sync(0xFFFFFFFFu, rs0, 1);
            rs0 += __shfl_xor_sync(0xFFFFFFFFu, rs0, 2);
            rs1 += __shfl_xor_sync(0xFFFFFFFFu, rs1, 1);
            rs1 += __shfl_xor_sync(0xFFFFFFFFu, rs1, 2);
            l0 = l0 * c0 + rs0;
            l1 = l1 * c1 + rs1;
            #pragma unroll
            for (int f = 0; f < 16; f++) {
                oacc[f][0] *= c0; oacc[f][1] *= c0;
                oacc[f][2] *= c1; oacc[f][3] *= c1;
            }

            #pragma unroll
            for (int ks2 = 0; ks2 < 4; ks2++) {
                int j0 = ks2 * 2, j1 = j0 + 1;
                uint32_t pah[4], pal[4];
                pack_hl(s[j0][0], s[j0][1], pah[0], pal[0]);
                pack_hl(s[j0][2], s[j0][3], pah[1], pal[1]);
                pack_hl(s[j1][0], s[j1][1], pah[2], pal[2]);
                pack_hl(s[j1][2], s[j1][3], pah[3], pal[3]);
                uint32_t vr = (uint32_t)(ks2 * 16 + (lid & 15));
                uint32_t vub = (uint32_t)(lid >> 4);
                #pragma unroll
                for (int ng = 0; ng < 8; ng++) {
                    uint32_t vh0, vh1, vh2, vh3, vl0, vl1, vl2, vl3;
                    uint32_t off = OFFA(vr, ng * 2 + vub);
                    LDSM4T(vh0, vh1, vh2, vh3, stg + 32768 + off);
                    LDSM4T(vl0, vl1, vl2, vl3, stg + 49152 + off);
                    MMA16816(oacc[ng * 2],     pah[0], pah[1], pah[2], pah[3], vh0, vh1);
                    MMA16816(oacc[ng * 2 + 1], pah[0], pah[1], pah[2], pah[3], vh2, vh3);
                    MMA16816(oacc[ng * 2],     pah[0], pah[1], pah[2], pah[3], vl0, vl1);
                    MMA16816(oacc[ng * 2 + 1], pah[0], pah[1], pah[2], pah[3], vl2, vl3);
                    MMA16816(oacc[ng * 2],     pal[0], pal[1], pal[2], pal[3], vh0, vh1);
                    MMA16816(oacc[ng * 2 + 1], pal[0], pal[1], pal[2], pal[3], vh2, vh3);
                }
            }
        }
        __syncthreads();
        if (it + 2 < nkt) kvload(it + 2, (it & 1) ? 0u : 65536u);
    }

    float inv0 = 1.f / l0, inv1 = 1.f / l1;
    size_t grow = (size_t)(b * T_SEQ + r0);
    #pragma unroll
    for (int f = 0; f < 16; f++) {
        int col = h * HDIM + f * 8 + (lid & 3) * 2;
        uint32_t hh, ll;
        pack_hl(oacc[f][0] * inv0, oacc[f][1] * inv0, hh, ll);
        *(uint32_t*)(OutH + grow * 4096 + col) = hh;
        *(uint32_t*)(OutL + grow * 4096 + col) = ll;
        pack_hl(oacc[f][2] * inv1, oacc[f][3] * inv1, hh, ll);
        *(uint32_t*)(OutH + (grow + 8) * 4096 + col) = hh;
        *(uint32_t*)(OutL + (grow + 8) * 4096 + col) = ll;
    }
}

// ================= launcher =================
extern "C" void kernel_launch(void* const* d_in, const int* in_sizes, int n_in,
                              void* d_out, int out_size)
{
    const float* x  = (const float*)d_in[0];
    const float* wq = (const float*)d_in[1];
    const float* wk = (const float*)d_in[2];
    const float* wv = (const float*)d_in[3];
    const float* wo = (const float*)d_in[4];
    const int*   sp = (n_in > 5) ? (const int*)d_in[5] : nullptr;
    float* out = (float*)d_out;
    (void)in_sizes; (void)out_size;

    float *gq, *gkv;
    cudaGetSymbolAddress((void**)&gq, g_q);
    cudaGetSymbolAddress((void**)&gkv, g_kv);
    __nv_bfloat16 *xh, *xl, *ah, *al, *qh, *ql, *kh, *kl, *vh, *vl;
    __nv_bfloat16 *wqh, *wql, *wkvh, *wkvl, *woh, *wol;
    float4* tab;
    cudaGetSymbolAddress((void**)&xh, g_xh);     cudaGetSymbolAddress((void**)&xl, g_xl);
    cudaGetSymbolAddress((void**)&ah, g_ah);     cudaGetSymbolAddress((void**)&al, g_al);
    cudaGetSymbolAddress((void**)&qh, g_qh);     cudaGetSymbolAddress((void**)&ql, g_ql);
    cudaGetSymbolAddress((void**)&kh, g_kh);     cudaGetSymbolAddress((void**)&kl, g_kl);
    cudaGetSymbolAddress((void**)&vh, g_vh);     cudaGetSymbolAddress((void**)&vl, g_vl);
    cudaGetSymbolAddress((void**)&wqh, g_wqh);   cudaGetSymbolAddress((void**)&wql, g_wql);
    cudaGetSymbolAddress((void**)&wkvh, g_wkvh); cudaGetSymbolAddress((void**)&wkvl, g_wkvl);
    cudaGetSymbolAddress((void**)&woh, g_woh);   cudaGetSymbolAddress((void**)&wol, g_wol);
    cudaGetSymbolAddress((void**)&tab, g_ropetab);

    cudaFuncSetAttribute(gemm3_kernel, cudaFuncAttributeMaxDynamicSharedMemorySize, GEMM_SMEM);
    cudaFuncSetAttribute(gemm3_big_kernel, cudaFuncAttributeMaxDynamicSharedMemorySize, BIG_SMEM);
    cudaFuncSetAttribute(attn_tc_kernel, cudaFuncAttributeMaxDynamicSharedMemorySize, ATT_SMEM);

    int n4x = BT * 4096 / 4;

    split_kernel<<<n4x / 256, 256>>>(x, xh, xl, n4x);
    ropetab_kernel<<<(1024 * 64) / 256, 256>>>(sp, tab);
    tsplit2_kernel<<<dim3(4096 / 32, 4096 / 64), 256>>>(wq, wqh, wql, 4096, 4096);
    tsplit2_kernel<<<dim3(1024 / 32, 4096 / 64), 256>>>(wk, wkvh, wkvl, 4096, 1024);
    tsplit2_kernel<<<dim3(1024 / 32, 4096 / 64), 256>>>(wv, wkvh + (size_t)1024 * 4096,
                                                        wkvl + (size_t)1024 * 4096, 4096, 1024);
    tsplit2_kernel<<<dim3(4096 / 32, 4096 / 64), 256>>>(wo, woh, wol, 4096, 4096);

    // big Q projection
    gemm3_big_kernel<<<dim3(4096 / 256, BT / 128), 256, BIG_SMEM>>>(xh, xl, wqh, wql, gq, BT, 4096, 4096);
    // merged K|V projection (N = 2048)
    gemm3_kernel<<<dim3(2048 / 128, BT / 128), 256, GEMM_SMEM>>>(xh, xl, wkvh, wkvl, gkv, BT, 2048, 4096);

    // RoPE (table) + bf16 hi/lo split (scale baked into q)
    rope_split_kernel<<<(BT * 2048) / 256, 256>>>(gq, 4096, qh, ql, 4096,
                                                  BT * 2048, tab, 0.08838834764831845f);
    rope_split_kernel<<<(BT * 512) / 256, 256>>>(gkv, 2048, kh, kl, 1024,
                                                 BT * 512, tab, 1.0f);
    splitstride_kernel<<<(BT * 256) / 256, 256>>>(gkv + 1024, 512, 256, vh, vl, BT * 256);

    // tensor-core flash attention (emits bf16 hi/lo directly)
    attn_tc_kernel<<<dim3(T_SEQ / 128, NH, B_SZ), 256, ATT_SMEM>>>(qh, ql, kh, kl, vh, vl, ah, al);

    // output projection
    gemm3_big_kernel<<<dim3(4096 / 256, BT / 128), 256, BIG_SMEM>>>(ah, al, woh, wol, out, BT, 4096, 4096);
}

// round 17
// speedup vs baseline: 1.5317x; 1.0166x over previous
#include <cuda_runtime.h>
#include <cuda_bf16.h>
#include <math.h>
#include <stdint.h>

#define B_SZ   2
#define T_SEQ  1024
#define BT     2048
#define NH     32
#define HDIM   128

// ================= scratch =================
__device__ float g_qkv[BT * 6144];
__device__ __nv_bfloat16 g_xh[BT * 4096], g_xl[BT * 4096];
__device__ __nv_bfloat16 g_ah[BT * 4096], g_al[BT * 4096];
__device__ __nv_bfloat16 g_qh[BT * 4096], g_ql[BT * 4096];
__device__ __nv_bfloat16 g_kh[BT * 1024], g_kl[BT * 1024];
__device__ __nv_bfloat16 g_vh[BT * 1024], g_vl[BT * 1024];
__device__ __nv_bfloat16 g_wqkvh[6144 * 4096], g_wqkvl[6144 * 4096];
__device__ __nv_bfloat16 g_woh[4096 * 4096], g_wol[4096 * 4096];
__device__ float4 g_ropetab[1024 * 64];

// ================= helpers =================
__device__ __forceinline__ uint32_t smem_u32(const void* p) {
    uint32_t a;
    asm("{ .reg .u64 t; cvta.to.shared.u64 t, %1; cvt.u32.u64 %0, t; }"
        : "=r"(a) : "l"(p));
    return a;
}
// GEMM tile swizzle: (rows)x32(k) bf16 tile
__device__ __forceinline__ uint32_t swz(uint32_t r, uint32_t u) {
    return ((r >> 1) << 7) | (((((r & 1) << 2) | u) ^ ((r >> 1) & 7)) << 4);
}
// attention tile swizzle: (rows)x128 bf16 tile, 16 16B-units/row
#define OFFA(r, u) (((uint32_t)(r)) * 256 + ((((uint32_t)(u)) ^ (((uint32_t)(r)) & 7)) << 4))

#define CP_ASYNC16(dst, src) \
    asm volatile("cp.async.cg.shared.global [%0], [%1], 16;" :: "r"(dst), "l"(src))
#define CP_COMMIT() asm volatile("cp.async.commit_group;" ::: "memory")
#define CP_WAIT0()  asm volatile("cp.async.wait_group 0;" ::: "memory")
#define CP_WAIT1()  asm volatile("cp.async.wait_group 1;" ::: "memory")
#define CP_WAIT2()  asm volatile("cp.async.wait_group 2;" ::: "memory")

#define LDSM4(r0, r1, r2, r3, a) \
    asm volatile("ldmatrix.sync.aligned.m8n8.x4.shared.b16 {%0,%1,%2,%3}, [%4];" \
        : "=r"(r0), "=r"(r1), "=r"(r2), "=r"(r3) : "r"(a))
#define LDSM4T(r0, r1, r2, r3, a) \
    asm volatile("ldmatrix.sync.aligned.m8n8.x4.trans.shared.b16 {%0,%1,%2,%3}, [%4];" \
        : "=r"(r0), "=r"(r1), "=r"(r2), "=r"(r3) : "r"(a))

#define MMA16816(c, a0, a1, a2, a3, b0, b1) \
    asm volatile("mma.sync.aligned.m16n8k16.row.col.f32.bf16.bf16.f32 " \
        "{%0,%1,%2,%3}, {%4,%5,%6,%7}, {%8,%9}, {%0,%1,%2,%3};" \
        : "+f"((c)[0]), "+f"((c)[1]), "+f"((c)[2]), "+f"((c)[3]) \
        : "r"(a0), "r"(a1), "r"(a2), "r"(a3), "r"(b0), "r"(b1))

__device__ __forceinline__ void pack_hl(float f0, float f1, uint32_t& h, uint32_t& l) {
    __nv_bfloat162 hh = __floats2bfloat162_rn(f0, f1);
    float r0 = f0 - __bfloat162float(hh.x);
    float r1 = f1 - __bfloat162float(hh.y);
    __nv_bfloat162 ll = __floats2bfloat162_rn(r0, r1);
    h = *(uint32_t*)&hh;
    l = *(uint32_t*)&ll;
}

// ============ rope table: tab[t][p] = (cos a0, sin a0, cos a1, sin a1) ============
__global__ void ropetab_kernel(const int* __restrict__ sp, float4* __restrict__ tab)
{
    int i = blockIdx.x * blockDim.x + threadIdx.x;   // 0..65535
    int t = i >> 6, p = i & 63;
    int start = (sp == nullptr) ? 0 : *sp;
    float tt = (float)(start + t);
    const float lf = 9.210340371976184f;
    int j0 = (2 * p) & 63;
    float a0 = tt * expf(-(float)j0       * (lf / 64.f));
    float a1 = tt * expf(-(float)(j0 + 1) * (lf / 64.f));
    float c0, s0, c1, s1;
    sincosf(a0, &s0, &c0);
    sincosf(a1, &s1, &c1);
    tab[i] = make_float4(c0, s0, c1, s1);
}

// ============ split fp32 -> bf16 hi/lo (row-major dense) ============
__global__ void split_kernel(const float* __restrict__ in,
                             __nv_bfloat16* __restrict__ hi,
                             __nv_bfloat16* __restrict__ lo, int n4)
{
    int i = blockIdx.x * blockDim.x + threadIdx.x;
    if (i >= n4) return;
    float4 v = ((const float4*)in)[i];
    uint32_t h0, l0, h1, l1;
    pack_hl(v.x, v.y, h0, l0);
    pack_hl(v.z, v.w, h1, l1);
    ((uint2*)hi)[i] = make_uint2(h0, h1);
    ((uint2*)lo)[i] = make_uint2(l0, l1);
}

// ============ strided split: in[row*in_stride4 + c4] (float4 units) ============
__global__ void splitstride_kernel(const float* __restrict__ in, int in_stride4,
                                   int cols4, __nv_bfloat16* __restrict__ hi,
                                   __nv_bfloat16* __restrict__ lo, int n4)
{
    int i = blockIdx.x * blockDim.x + threadIdx.x;
    if (i >= n4) return;
    int row = i / cols4;
    int c4 = i - row * cols4;
    float4 v = ((const float4*)in)[(size_t)row * in_stride4 + c4];
    int o = row * cols4 + c4;
    uint32_t h0, l0, h1, l1;
    pack_hl(v.x, v.y, h0, l0);
    pack_hl(v.z, v.w, h1, l1);
    ((uint2*)hi)[o] = make_uint2(h0, h1);
    ((uint2*)lo)[o] = make_uint2(l0, l1);
}

// ============ transpose + split: W[K][N] fp32 -> Wt[N][K] bf16 hi/lo ============
__global__ __launch_bounds__(256) void tsplit2_kernel(
    const float* __restrict__ W, __nv_bfloat16* __restrict__ hi,
    __nv_bfloat16* __restrict__ lo, int K, int N)
{
    __shared__ float s[32][66];
    const int n0 = blockIdx.x * 32, k0 = blockIdx.y * 64;
    const int tid = threadIdx.x;
    #pragma unroll
    for (int i = 0; i < 8; i++) {
        int idx = tid + i * 256;
        int r = idx >> 5;
        int c = idx & 31;
        s[c][r] = W[(size_t)(k0 + r) * N + n0 + c];
    }
    __syncthreads();
    #pragma unroll
    for (int i = 0; i < 4; i++) {
        int p = tid + i * 256;
        int row = p >> 5;
        int pr = p & 31;
        float2 v = *(float2*)&s[row][pr * 2];
        uint32_t h, l;
        pack_hl(v.x, v.y, h, l);
        size_t o = (size_t)(n0 + row) * K + k0 + pr * 2;
        *(uint32_t*)(hi + o) = h;
        *(uint32_t*)(lo + o) = l;
    }
}

// ============ RoPE (table) + split (strided in/out) ============
__global__ void rope_split_kernel(const float* __restrict__ in, int in_stride,
                                  __nv_bfloat16* __restrict__ hi,
                                  __nv_bfloat16* __restrict__ lo, int out_stride,
                                  int total_pairs, const float4* __restrict__ tab,
                                  float scale)
{
    int idx = blockIdx.x * blockDim.x + threadIdx.x;
    if (idx >= total_pairs) return;
    int halfout = out_stride >> 1;
    int row = idx / halfout;
    int p   = idx - row * halfout;
    int c0  = p * 2;
    int pp  = (c0 & (HDIM - 1)) >> 1;
    float4 cs = tab[(row & (T_SEQ - 1)) * 64 + pp];
    const float* base = in + (size_t)row * in_stride + c0;
    float x0 = base[0], x1 = base[1];
    float y0 = (x0 * cs.x - x1 * cs.y) * scale;
    float y1 = (x1 * cs.z + x0 * cs.w) * scale;
    uint32_t h, l;
    pack_hl(y0, y1, h, l);
    *(uint32_t*)(hi + (size_t)row * out_stride + c0) = h;
    *(uint32_t*)(lo + (size_t)row * out_stride + c0) = l;
}

// ============ bf16x3 GEMM 128x256 (QKV and O) ============
#define KC      32
#define NSTB    4
#define A_TB    8192
#define B_TB    16384
#define STAGE_BB (2 * A_TB + 2 * B_TB)
#define BIG_SMEM (NSTB * STAGE_BB)

__global__ __launch_bounds__(256, 1) void gemm3_big_kernel(
    const __nv_bfloat16* __restrict__ Ah, const __nv_bfloat16* __restrict__ Al,
    const __nv_bfloat16* __restrict__ Bh, const __nv_bfloat16* __restrict__ Bl,
    float* __restrict__ C, int M, int N, int K)
{
    extern __shared__ char smem[];
    const uint32_t sb = smem_u32(smem);
    const int tid = threadIdx.x, wid = tid >> 5, lid = tid & 31;
    const int m0 = blockIdx.y * 128, n0 = blockIdx.x * 256;
    const int warp_m = wid & 1, warp_n = wid >> 1;
    const int NCH = K / KC;

    uint32_t rel_a[4][2], rel_b[4][2];
    {
        uint32_t ar = (uint32_t)(warp_m * 64 + (lid & 15));
        uint32_t au = (uint32_t)(lid >> 4);
        #pragma unroll
        for (int mi = 0; mi < 4; mi++)
            #pragma unroll
            for (int k16 = 0; k16 < 2; k16++)
                rel_a[mi][k16] = swz(ar + mi * 16, au + k16 * 2);
        uint32_t br = (uint32_t)(warp_n * 64 + (lid & 7) + ((lid >> 4) << 3));
        uint32_t bu = (uint32_t)((lid >> 3) & 1);
        #pragma unroll
        for (int ng = 0; ng < 4; ng++)
            #pragma unroll
            for (int k16 = 0; k16 < 2; k16++)
                rel_b[ng][k16] = swz(br + ng * 16, bu + k16 * 2);
    }

    float acc[4][8][4];
    #pragma unroll
    for (int mi = 0; mi < 4; mi++)
        #pragma unroll
        for (int ni = 0; ni < 8; ni++)
            #pragma unroll
            for (int j = 0; j < 4; j++) acc[mi][ni][j] = 0.f;

    auto load_stage = [&](int s, int chunk) {
        const int k0 = chunk * KC;
        const uint32_t st = sb + s * STAGE_BB;
        #pragma unroll
        for (int t = 0; t < 12; t++) {
            int g = t * 256 + tid;
            uint32_t dst;
            const __nv_bfloat16* src;
            if (g < 1024) {
                int r = (g & 511) >> 2, u = g & 3;
                dst = st + (g >> 9) * A_TB + swz(r, u);
                src = ((g >> 9) ? Al : Ah) + (size_t)(m0 + r) * K + k0 + u * 8;
            } else {
                int w = g - 1024;
                int r = (w & 1023) >> 2, u = w & 3;
                dst = st + 2 * A_TB + (w >> 10) * B_TB + swz(r, u);
                src = ((w >> 10) ? Bl : Bh) + (size_t)(n0 + r) * K + k0 + u * 8;
            }
            CP_ASYNC16(dst, src);
        }
    };

    load_stage(0, 0); CP_COMMIT();
    load_stage(1, 1); CP_COMMIT();
    load_stage(2, 2); CP_COMMIT();

    for (int i = 0; i < NCH; i++) {
        CP_WAIT2();
        __syncthreads();
        int nxt = i + NSTB - 1;
        if (nxt < NCH) load_stage(nxt % NSTB, nxt);
        CP_COMMIT();

        const uint32_t st = sb + (i % NSTB) * STAGE_BB;
        const uint32_t ah_b = st, al_b = st + A_TB;
        const uint32_t bh_b = st + 2 * A_TB, bl_b = st + 2 * A_TB + B_TB;

        #pragma unroll
        for (int k16 = 0; k16 < 2; k16++) {
            uint32_t afh[4][4], afl[4][4];
            #pragma unroll
            for (int mi = 0; mi < 4; mi++) {
                LDSM4(afh[mi][0], afh[mi][1], afh[mi][2], afh[mi][3], ah_b + rel_a[mi][k16]);
                LDSM4(afl[mi][0], afl[mi][1], afl[mi][2], afl[mi][3], al_b + rel_a[mi][k16]);
            }
            #pragma unroll
            for (int ng = 0; ng < 4; ng++) {
                uint32_t bfh[4], bfl[4];
                LDSM4(bfh[0], bfh[1], bfh[2], bfh[3], bh_b + rel_b[ng][k16]);
                LDSM4(bfl[0], bfl[1], bfl[2], bfl[3], bl_b + rel_b[ng][k16]);
                #pragma unroll
                for (int mi = 0; mi < 4; mi++)
                    #pragma unroll
                    for (int rp = 0; rp < 2; rp++) {
                        float* a = acc[mi][ng * 2 + rp];
                        MMA16816(a, afh[mi][0], afh[mi][1], afh[mi][2], afh[mi][3],
                                 bfh[rp * 2], bfh[rp * 2 + 1]);
                        MMA16816(a, afh[mi][0], afh[mi][1], afh[mi][2], afh[mi][3],
                                 bfl[rp * 2], bfl[rp * 2 + 1]);
                        MMA16816(a, afl[mi][0], afl[mi][1], afl[mi][2], afl[mi][3],
                                 bfh[rp * 2], bfh[rp * 2 + 1]);
                    }
            }
        }
    }

    #pragma unroll
    for (int mi = 0; mi < 4; mi++) {
        int row = m0 + warp_m * 64 + mi * 16 + (lid >> 2);
        #pragma unroll
        for (int ni = 0; ni < 8; ni++) {
            int col = n0 + warp_n * 64 + ni * 8 + (lid & 3) * 2;
            *(float2*)&C[(size_t)row * N + col] = make_float2(acc[mi][ni][0], acc[mi][ni][1]);
            *(float2*)&C[(size_t)(row + 8) * N + col] = make_float2(acc[mi][ni][2], acc[mi][ni][3]);
        }
    }
}

// ============ Tensor-core flash attention (causal, GQA, bf16x3) ============
#define ATT_SMEM 131072

__global__ __launch_bounds__(256, 1) void attn_tc_kernel(
    const __nv_bfloat16* __restrict__ Qh, const __nv_bfloat16* __restrict__ Ql,
    const __nv_bfloat16* __restrict__ Kh, const __nv_bfloat16* __restrict__ Kl,
    const __nv_bfloat16* __restrict__ Vh, const __nv_bfloat16* __restrict__ Vl,
    __nv_bfloat16* __restrict__ OutH, __nv_bfloat16* __restrict__ OutL)
{
    extern __shared__ char smem[];
    const uint32_t sb = smem_u32(smem);
    const int tid = threadIdx.x, wid = tid >> 5, lid = tid & 31;
    const int b = blockIdx.z, h = blockIdx.y;
    const int m0 = ((int)gridDim.x - 1 - (int)blockIdx.x) * 128;   // heavy first
    const int kvh = h >> 2;

    #pragma unroll
    for (int i = 0; i < 16; i++) {
        int idx = i * 256 + tid;
        int t = idx >> 11, w = idx & 2047;
        int r = w >> 4, u = w & 15;
        const __nv_bfloat16* src = (t ? Ql : Qh)
            + (size_t)(b * T_SEQ + m0 + r) * 4096 + h * HDIM + u * 8;
        CP_ASYNC16(sb + t * 32768 + OFFA(r, u), src);
    }
    CP_COMMIT();

    auto kvload = [&](int kt, uint32_t base) {
        #pragma unroll
        for (int i = 0; i < 16; i++) {
            int idx = i * 256 + tid;
            int t = idx >> 10, w = idx & 1023;
            int r = w >> 4, u = w & 15;
            const __nv_bfloat16* arr = (t == 0) ? Kh : (t == 1) ? Kl : (t == 2) ? Vh : Vl;
            const __nv_bfloat16* src = arr
                + (size_t)(b * T_SEQ + kt * 64 + r) * 1024 + kvh * HDIM + u * 8;
            CP_ASYNC16(sb + base + t * 16384 + OFFA(r, u), src);
        }
        CP_COMMIT();
    };

    const int nkt = (m0 + 128) / 64;
    kvload(0, 65536);

    CP_WAIT1();
    __syncthreads();

    uint32_t qfh[8][4], qfl[8][4];
    {
        uint32_t r = (uint32_t)(wid * 16 + (lid & 15));
        uint32_t ub = (uint32_t)(lid >> 4);
        #pragma unroll
        for (int ks = 0; ks < 8; ks++) {
            uint32_t off = OFFA(r, ks * 2 + ub);
            LDSM4(qfh[ks][0], qfh[ks][1], qfh[ks][2], qfh[ks][3], sb + off);
            LDSM4(qfl[ks][0], qfl[ks][1], qfl[ks][2], qfl[ks][3], sb + 32768 + off);
        }
    }
    __syncthreads();
    if (nkt > 1) kvload(1, 0);

    float oacc[16][4];
    #pragma unroll
    for (int f = 0; f < 16; f++)
        #pragma unroll
        for (int j = 0; j < 4; j++) oacc[f][j] = 0.f;
    float mr0 = -INFINITY, mr1 = -INFINITY, l0 = 0.f, l1 = 0.f;

    const int row_lo = m0 + wid * 16;
    const int r0 = row_lo + (lid >> 2);

    for (int it = 0; it < nkt; it++) {
        if (it + 1 < nkt) { CP_WAIT1(); } else { CP_WAIT0(); }
        __syncthreads();
        const uint32_t stg = sb + ((it & 1) ? 0u : 65536u);
        const int ktb = it * 64;

        if (ktb <= row_lo + 15) {
            float s[8][4];
            #pragma unroll
            for (int j = 0; j < 8; j++)
                #pragma unroll
                for (int q = 0; q < 4; q++) s[j][q] = 0.f;

            uint32_t br = (uint32_t)((lid & 7) + ((lid >> 4) << 3));
            uint32_t bu = (uint32_t)((lid >> 3) & 1);
            #pragma unroll
            for (int ks = 0; ks < 8; ks++) {
                #pragma unroll
                for (int jj = 0; jj < 4; jj++) {
                    uint32_t kh0, kh1, kh2, kh3, kl0, kl1, kl2, kl3;
                    uint32_t off = OFFA(jj * 16 + br, ks * 2 + bu);
                    LDSM4(kh0, kh1, kh2, kh3, stg + off);
                    LDSM4(kl0, kl1, kl2, kl3, stg + 16384 + off);
                    MMA16816(s[jj * 2],     qfh[ks][0], qfh[ks][1], qfh[ks][2], qfh[ks][3], kh0, kh1);
                    MMA16816(s[jj * 2 + 1], qfh[ks][0], qfh[ks][1], qfh[ks][2], qfh[ks][3], kh2, kh3);
                    MMA16816(s[jj * 2],     qfh[ks][0], qfh[ks][1], qfh[ks][2], qfh[ks][3], kl0, kl1);
                    MMA16816(s[jj * 2 + 1], qfh[ks][0], qfh[ks][1], qfh[ks][2], qfh[ks][3], kl2, kl3);
                    MMA16816(s[jj * 2],     qfl[ks][0], qfl[ks][1], qfl[ks][2], qfl[ks][3], kh0, kh1);
                    MMA16816(s[jj * 2 + 1], qfl[ks][0], qfl[ks][1], qfl[ks][2], qfl[ks][3], kh2, kh3);
                }
            }

            if (ktb + 63 > row_lo) {
                #pragma unroll
                for (int j = 0; j < 8; j++) {
                    int c = ktb + j * 8 + (lid & 3) * 2;
                    if (c > r0)         s[j][0] = -INFINITY;
                    if (c + 1 > r0)     s[j][1] = -INFINITY;
                    if (c > r0 + 8)     s[j][2] = -INFINITY;
                    if (c + 1 > r0 + 8) s[j][3] = -INFINITY;
                }
            }

            float mx0 = -INFINITY, mx1 = -INFINITY;
            #pragma unroll
            for (int j = 0; j < 8; j++) {
                mx0 = fmaxf(mx0, fmaxf(s[j][0], s[j][1]));
                mx1 = fmaxf(mx1, fmaxf(s[j][2], s[j][3]));
            }
            mx0 = fmaxf(mx0, __shfl_xor_sync(0xFFFFFFFFu, mx0, 1));
            mx0 = fmaxf(mx0, __shfl_xor_sync(0xFFFFFFFFu, mx0, 2));
            mx1 = fmaxf(mx1, __shfl_xor_sync(0xFFFFFFFFu, mx1, 1));
            mx1 = fmaxf(mx1, __shfl_xor_sync(0xFFFFFFFFu, mx1, 2));
            float mn0 = fmaxf(mr0, mx0), mn1 = fmaxf(mr1, mx1);
            float c0 = __expf(mr0 - mn0), c1 = __expf(mr1 - mn1);
            mr0 = mn0; mr1 = mn1;
            float rs0 = 0.f, rs1 = 0.f;
            #pragma unroll
            for (int j = 0; j < 8; j++) {
                s[j][0] = __expf(s[j][0] - mn0);
                s[j][1] = __expf(s[j][1] - mn0);
                s[j][2] = __expf(s[j][2] - mn1);
                s[j][3] = __expf(s[j][3] - mn1);
                rs0 += s[j][0] + s[j][1];
                rs1 += s[j][2] + s[j][3];
            }
            rs0 += __shfl_xor_sync(0xFFFFFFFFu, rs0, 1);
            rs0 += __shfl_xor_sync(0xFFFFFFFFu, rs0, 2);
            rs1 += __shfl_xor_sync(0xFFFFFFFFu, rs1, 1);
            rs1 += __shfl_xor_sync(0xFFFFFFFFu, rs1, 2);
            l0 = l0 * c0 + rs0;
            l1 = l1 * c1 + rs1;
            #pragma unroll
            for (int f = 0; f < 16; f++) {
                oacc[f][0] *= c0; oacc[f][1] *= c0;
                oacc[f][2] *= c1; oacc[f][3] *= c1;
            }

            #pragma unroll
            for (int ks2 = 0; ks2 < 4; ks2++) {
                int j0 = ks2 * 2, j1 = j0 + 1;
                uint32_t pah[4], pal[4];
                pack_hl(s[j0][0], s[j0][1], pah[0], pal[0]);
                pack_hl(s[j0][2], s[j0][3], pah[1], pal[1]);
                pack_hl(s[j1][0], s[j1][1], pah[2], pal[2]);
                pack_hl(s[j1][2], s[j1][3], pah[3], pal[3]);
                uint32_t vr = (uint32_t)(ks2 * 16 + (lid & 15));
                uint32_t vub = (uint32_t)(lid >> 4);
                #pragma unroll
                for (int ng = 0; ng < 8; ng++) {
                    uint32_t vh0, vh1, vh2, vh3, vl0, vl1, vl2, vl3;
                    uint32_t off = OFFA(vr, ng * 2 + vub);
                    LDSM4T(vh0, vh1, vh2, vh3, stg + 32768 + off);
                    LDSM4T(vl0, vl1, vl2, vl3, stg + 49152 + off);
                    MMA16816(oacc[ng * 2],     pah[0], pah[1], pah[2], pah[3], vh0, vh1);
                    MMA16816(oacc[ng * 2 + 1], pah[0], pah[1], pah[2], pah[3], vh2, vh3);
                    MMA16816(oacc[ng * 2],     pah[0], pah[1], pah[2], pah[3], vl0, vl1);
                    MMA16816(oacc[ng * 2 + 1], pah[0], pah[1], pah[2], pah[3], vl2, vl3);
                    MMA16816(oacc[ng * 2],     pal[0], pal[1], pal[2], pal[3], vh0, vh1);
                    MMA16816(oacc[ng * 2 + 1], pal[0], pal[1], pal[2], pal[3], vh2, vh3);
                }
            }
        }
        __syncthreads();
        if (it + 2 < nkt) kvload(it + 2, (it & 1) ? 0u : 65536u);
    }

    float inv0 = 1.f / l0, inv1 = 1.f / l1;
    size_t grow = (size_t)(b * T_SEQ + r0);
    #pragma unroll
    for (int f = 0; f < 16; f++) {
        int col = h * HDIM + f * 8 + (lid & 3) * 2;
        uint32_t hh, ll;
        pack_hl(oacc[f][0] * inv0, oacc[f][1] * inv0, hh, ll);
        *(uint32_t*)(OutH + grow * 4096 + col) = hh;
        *(uint32_t*)(OutL + grow * 4096 + col) = ll;
        pack_hl(oacc[f][2] * inv1, oacc[f][3] * inv1, hh, ll);
        *(uint32_t*)(OutH + (grow + 8) * 4096 + col) = hh;
        *(uint32_t*)(OutL + (grow + 8) * 4096 + col) = ll;
    }
}

// ================= launcher =================
extern "C" void kernel_launch(void* const* d_in, const int* in_sizes, int n_in,
                              void* d_out, int out_size)
{
    const float* x  = (const float*)d_in[0];
    const float* wq = (const float*)d_in[1];
    const float* wk = (const float*)d_in[2];
    const float* wv = (const float*)d_in[3];
    const float* wo = (const float*)d_in[4];
    const int*   sp = (n_in > 5) ? (const int*)d_in[5] : nullptr;
    float* out = (float*)d_out;
    (void)in_sizes; (void)out_size;

    float* gqkv;
    cudaGetSymbolAddress((void**)&gqkv, g_qkv);
    __nv_bfloat16 *xh, *xl, *ah, *al, *qh, *ql, *kh, *kl, *vh, *vl;
    __nv_bfloat16 *wqkvh, *wqkvl, *woh, *wol;
    float4* tab;
    cudaGetSymbolAddress((void**)&xh, g_xh);       cudaGetSymbolAddress((void**)&xl, g_xl);
    cudaGetSymbolAddress((void**)&ah, g_ah);       cudaGetSymbolAddress((void**)&al, g_al);
    cudaGetSymbolAddress((void**)&qh, g_qh);       cudaGetSymbolAddress((void**)&ql, g_ql);
    cudaGetSymbolAddress((void**)&kh, g_kh);       cudaGetSymbolAddress((void**)&kl, g_kl);
    cudaGetSymbolAddress((void**)&vh, g_vh);       cudaGetSymbolAddress((void**)&vl, g_vl);
    cudaGetSymbolAddress((void**)&wqkvh, g_wqkvh); cudaGetSymbolAddress((void**)&wqkvl, g_wqkvl);
    cudaGetSymbolAddress((void**)&woh, g_woh);     cudaGetSymbolAddress((void**)&wol, g_wol);
    cudaGetSymbolAddress((void**)&tab, g_ropetab);

    cudaFuncSetAttribute(gemm3_big_kernel, cudaFuncAttributeMaxDynamicSharedMemorySize, BIG_SMEM);
    cudaFuncSetAttribute(attn_tc_kernel, cudaFuncAttributeMaxDynamicSharedMemorySize, ATT_SMEM);

    int n4x = BT * 4096 / 4;

    split_kernel<<<n4x / 256, 256>>>(x, xh, xl, n4x);
    ropetab_kernel<<<(1024 * 64) / 256, 256>>>(sp, tab);
    // weights -> one concatenated [6144][4096] bf16 hi/lo buffer
    tsplit2_kernel<<<dim3(4096 / 32, 4096 / 64), 256>>>(wq, wqkvh, wqkvl, 4096, 4096);
    tsplit2_kernel<<<dim3(1024 / 32, 4096 / 64), 256>>>(wk, wqkvh + (size_t)4096 * 4096,
                                                        wqkvl + (size_t)4096 * 4096, 4096, 1024);
    tsplit2_kernel<<<dim3(1024 / 32, 4096 / 64), 256>>>(wv, wqkvh + (size_t)5120 * 4096,
                                                        wqkvl + (size_t)5120 * 4096, 4096, 1024);
    tsplit2_kernel<<<dim3(4096 / 32, 4096 / 64), 256>>>(wo, woh, wol, 4096, 4096);

    // fused Q|K|V projection: C[2048, 6144]
    gemm3_big_kernel<<<dim3(6144 / 256, BT / 128), 256, BIG_SMEM>>>(
        xh, xl, wqkvh, wqkvl, gqkv, BT, 6144, 4096);

    // RoPE (table) + bf16 hi/lo split; scale baked into q
    rope_split_kernel<<<(BT * 2048) / 256, 256>>>(gqkv, 6144, qh, ql, 4096,
                                                  BT * 2048, tab, 0.08838834764831845f);
    rope_split_kernel<<<(BT * 512) / 256, 256>>>(gqkv + 4096, 6144, kh, kl, 1024,
                                                 BT * 512, tab, 1.0f);
    splitstride_kernel<<<(BT * 256) / 256, 256>>>(gqkv + 5120, 1536, 256, vh, vl, BT * 256);

    // tensor-core flash attention (emits bf16 hi/lo directly)
    attn_tc_kernel<<<dim3(T_SEQ / 128, NH, B_SZ), 256, ATT_SMEM>>>(qh, ql, kh, kl, vh, vl, ah, al);

    // output projection
    gemm3_big_kernel<<<dim3(4096 / 256, BT / 128), 256, BIG_SMEM>>>(
        ah, al, woh, wol, out, BT, 4096, 4096);
}